// round 1
// baseline (speedup 1.0000x reference)
#include <cuda_runtime.h>

#define S_LEN  4096
#define BATCH  2
#define NH     12
#define DH     64
#define DMODEL 768
#define MROWS  (BATCH * S_LEN)   // 8192

// Scratch (static device globals; allocation-free rule)
__device__ __align__(128) float g_q[BATCH * NH * S_LEN * DH];
__device__ __align__(128) float g_k[BATCH * NH * S_LEN * DH];
__device__ __align__(128) float g_v[BATCH * NH * S_LEN * DH];
__device__ __align__(128) float g_ctx[MROWS * DMODEL];

// ---------------------------------------------------------------------------
// Tiled GEMM core: 64x64 tile, BK=16, 256 threads, 4x4 microtile per thread.
// ---------------------------------------------------------------------------

__global__ __launch_bounds__(256) void qkv_gemm(
    const float* __restrict__ x, const float* __restrict__ Wq,
    const float* __restrict__ Wk, const float* __restrict__ Wv)
{
    const float* W;
    float* out;
    float scale;
    if (blockIdx.z == 0)      { W = Wq; out = g_q; scale = 0.125f; }  // 1/sqrt(64) folded into Q
    else if (blockIdx.z == 1) { W = Wk; out = g_k; scale = 1.0f; }
    else                      { W = Wv; out = g_v; scale = 1.0f; }

    __shared__ __align__(16) float As[16][64];   // A transposed: As[k][m]
    __shared__ __align__(16) float Bs[16][64];   // Bs[k][n]

    const int tid = threadIdx.x;
    const int tx = tid & 15, ty = tid >> 4;
    const int row0 = blockIdx.y * 64, col0 = blockIdx.x * 64;

    float acc[4][4];
    #pragma unroll
    for (int r = 0; r < 4; r++)
        #pragma unroll
        for (int c = 0; c < 4; c++) acc[r][c] = 0.0f;

    const int arow = tid >> 2, acc4 = (tid & 3) << 2;
    const int brow = tid >> 4, bc   = (tid & 15) << 2;

    for (int k0 = 0; k0 < DMODEL; k0 += 16) {
        float4 av = *(const float4*)(x + (size_t)(row0 + arow) * DMODEL + k0 + acc4);
        As[acc4 + 0][arow] = av.x;
        As[acc4 + 1][arow] = av.y;
        As[acc4 + 2][arow] = av.z;
        As[acc4 + 3][arow] = av.w;
        *(float4*)(&Bs[brow][bc]) =
            *(const float4*)(W + (size_t)(k0 + brow) * DMODEL + col0 + bc);
        __syncthreads();

        #pragma unroll
        for (int kk = 0; kk < 16; kk++) {
            float4 a4 = *(const float4*)(&As[kk][ty << 2]);
            float4 b4 = *(const float4*)(&Bs[kk][tx << 2]);
            float avr[4] = {a4.x, a4.y, a4.z, a4.w};
            float bvr[4] = {b4.x, b4.y, b4.z, b4.w};
            #pragma unroll
            for (int r = 0; r < 4; r++)
                #pragma unroll
                for (int c = 0; c < 4; c++)
                    acc[r][c] += avr[r] * bvr[c];
        }
        __syncthreads();
    }

    // Store to [B, H, S, DH]. col0 is a multiple of 64 == DH, so one head per tile.
    const int h = col0 >> 6;
    #pragma unroll
    for (int r = 0; r < 4; r++) {
        int m = row0 + (ty << 2) + r;
        int b = m >> 12;         // / 4096
        int s = m & 4095;
        float4 o = make_float4(acc[r][0] * scale, acc[r][1] * scale,
                               acc[r][2] * scale, acc[r][3] * scale);
        *(float4*)(out + (((size_t)(b * NH + h) * S_LEN + s) << 6) + (tx << 2)) = o;
    }
}

__global__ __launch_bounds__(256) void out_gemm(
    const float* __restrict__ Wo, const float* __restrict__ bo,
    float* __restrict__ out)
{
    __shared__ __align__(16) float As[16][64];
    __shared__ __align__(16) float Bs[16][64];

    const int tid = threadIdx.x;
    const int tx = tid & 15, ty = tid >> 4;
    const int row0 = blockIdx.y * 64, col0 = blockIdx.x * 64;

    float acc[4][4];
    #pragma unroll
    for (int r = 0; r < 4; r++)
        #pragma unroll
        for (int c = 0; c < 4; c++) acc[r][c] = 0.0f;

    const int arow = tid >> 2, acc4 = (tid & 3) << 2;
    const int brow = tid >> 4, bc   = (tid & 15) << 2;

    for (int k0 = 0; k0 < DMODEL; k0 += 16) {
        float4 av = *(const float4*)(g_ctx + (size_t)(row0 + arow) * DMODEL + k0 + acc4);
        As[acc4 + 0][arow] = av.x;
        As[acc4 + 1][arow] = av.y;
        As[acc4 + 2][arow] = av.z;
        As[acc4 + 3][arow] = av.w;
        *(float4*)(&Bs[brow][bc]) =
            *(const float4*)(Wo + (size_t)(k0 + brow) * DMODEL + col0 + bc);
        __syncthreads();

        #pragma unroll
        for (int kk = 0; kk < 16; kk++) {
            float4 a4 = *(const float4*)(&As[kk][ty << 2]);
            float4 b4 = *(const float4*)(&Bs[kk][tx << 2]);
            float avr[4] = {a4.x, a4.y, a4.z, a4.w};
            float bvr[4] = {b4.x, b4.y, b4.z, b4.w};
            #pragma unroll
            for (int r = 0; r < 4; r++)
                #pragma unroll
                for (int c = 0; c < 4; c++)
                    acc[r][c] += avr[r] * bvr[c];
        }
        __syncthreads();
    }

    float4 bias = *(const float4*)(bo + col0 + (tx << 2));
    #pragma unroll
    for (int r = 0; r < 4; r++) {
        int m = row0 + (ty << 2) + r;
        float4 o = make_float4(acc[r][0] + bias.x, acc[r][1] + bias.y,
                               acc[r][2] + bias.z, acc[r][3] + bias.w);
        *(float4*)(out + (size_t)m * DMODEL + col0 + (tx << 2)) = o;
    }
}

// ---------------------------------------------------------------------------
// Flash attention, causal. 64 q-rows per block, 64 k-cols per tile.
// Qt/Kt stored transposed (k-major) with XOR swizzle for conflict-free float4
// shared reads. Kt and Ps share one buffer (disjoint live ranges).
// ---------------------------------------------------------------------------

__global__ __launch_bounds__(256) void flash_attn()
{
    __shared__ __align__(16) float Qt[64 * 64];     // transposed + swizzled
    __shared__ __align__(16) float KtPs[64 * 64];   // Kt (transposed+swizzled) / Ps (natural)
    __shared__ __align__(16) float Vs[64 * 64];     // natural [key][d]

    const int tid = threadIdx.x;
    const int tx = tid & 15, ty = tid >> 4;
    const int qt = blockIdx.x;
    const int bh = blockIdx.y;

    const float* qp = g_q + (size_t)bh * S_LEN * DH;
    const float* kp = g_k + (size_t)bh * S_LEN * DH;
    const float* vp = g_v + (size_t)bh * S_LEN * DH;

    // Load Q tile transposed + swizzled: element (d, r) -> Qt[d*64 + ((r/4 ^ (d&15))<<2) + (r&3)]
    #pragma unroll
    for (int i = tid; i < 1024; i += 256) {
        int r = i >> 4;
        int d4 = (i & 15) << 2;
        float4 v = *(const float4*)(qp + (((size_t)qt * 64 + r) << 6) + d4);
        int j = r >> 2, sub = r & 3;
        Qt[(d4 + 0) * 64 + ((j ^ ((d4 + 0) & 15)) << 2) + sub] = v.x;
        Qt[(d4 + 1) * 64 + ((j ^ ((d4 + 1) & 15)) << 2) + sub] = v.y;
        Qt[(d4 + 2) * 64 + ((j ^ ((d4 + 2) & 15)) << 2) + sub] = v.z;
        Qt[(d4 + 3) * 64 + ((j ^ ((d4 + 3) & 15)) << 2) + sub] = v.w;
    }

    float mrow[4], lrow[4], acc[4][4];
    #pragma unroll
    for (int r = 0; r < 4; r++) {
        mrow[r] = -1e30f;
        lrow[r] = 0.0f;
        #pragma unroll
        for (int c = 0; c < 4; c++) acc[r][c] = 0.0f;
    }

    for (int kt = 0; kt <= qt; kt++) {
        __syncthreads();   // previous tile's Ps/Vs reads done; Qt writes visible on first iter

        // Load K transposed+swizzled into KtPs; V natural into Vs
        #pragma unroll
        for (int i = tid; i < 1024; i += 256) {
            int r = i >> 4;
            int d4 = (i & 15) << 2;
            float4 kv = *(const float4*)(kp + (((size_t)kt * 64 + r) << 6) + d4);
            int j = r >> 2, sub = r & 3;
            KtPs[(d4 + 0) * 64 + ((j ^ ((d4 + 0) & 15)) << 2) + sub] = kv.x;
            KtPs[(d4 + 1) * 64 + ((j ^ ((d4 + 1) & 15)) << 2) + sub] = kv.y;
            KtPs[(d4 + 2) * 64 + ((j ^ ((d4 + 2) & 15)) << 2) + sub] = kv.z;
            KtPs[(d4 + 3) * 64 + ((j ^ ((d4 + 3) & 15)) << 2) + sub] = kv.w;
            *(float4*)(&Vs[(r << 6) + d4]) =
                *(const float4*)(vp + (((size_t)kt * 64 + r) << 6) + d4);
        }
        __syncthreads();

        // S = Q K^T  (Q pre-scaled by 1/sqrt(Dh))
        float s[4][4];
        #pragma unroll
        for (int r = 0; r < 4; r++)
            #pragma unroll
            for (int c = 0; c < 4; c++) s[r][c] = 0.0f;

        #pragma unroll 8
        for (int kk = 0; kk < 64; kk++) {
            float4 q4 = *(const float4*)(&Qt[(kk << 6) + ((ty ^ (kk & 15)) << 2)]);
            float4 k4 = *(const float4*)(&KtPs[(kk << 6) + ((tx ^ (kk & 15)) << 2)]);
            float qv[4] = {q4.x, q4.y, q4.z, q4.w};
            float kv[4] = {k4.x, k4.y, k4.z, k4.w};
            #pragma unroll
            for (int r = 0; r < 4; r++)
                #pragma unroll
                for (int c = 0; c < 4; c++)
                    s[r][c] += qv[r] * kv[c];
        }

        // Causal mask on diagonal tile
        if (kt == qt) {
            #pragma unroll
            for (int r = 0; r < 4; r++)
                #pragma unroll
                for (int c = 0; c < 4; c++)
                    if ((tx << 2) + c > (ty << 2) + r) s[r][c] = -1e30f;
        }

        // Online softmax (row reduce over 16 lanes of tx)
        #pragma unroll
        for (int r = 0; r < 4; r++) {
            float mx = fmaxf(fmaxf(s[r][0], s[r][1]), fmaxf(s[r][2], s[r][3]));
            mx = fmaxf(mx, __shfl_xor_sync(0xffffffffu, mx, 1, 16));
            mx = fmaxf(mx, __shfl_xor_sync(0xffffffffu, mx, 2, 16));
            mx = fmaxf(mx, __shfl_xor_sync(0xffffffffu, mx, 4, 16));
            mx = fmaxf(mx, __shfl_xor_sync(0xffffffffu, mx, 8, 16));
            float mn = fmaxf(mrow[r], mx);
            float alpha = __expf(mrow[r] - mn);
            mrow[r] = mn;
            float p0 = __expf(s[r][0] - mn);
            float p1 = __expf(s[r][1] - mn);
            float p2 = __expf(s[r][2] - mn);
            float p3 = __expf(s[r][3] - mn);
            float ls = p0 + p1 + p2 + p3;
            ls += __shfl_xor_sync(0xffffffffu, ls, 1, 16);
            ls += __shfl_xor_sync(0xffffffffu, ls, 2, 16);
            ls += __shfl_xor_sync(0xffffffffu, ls, 4, 16);
            ls += __shfl_xor_sync(0xffffffffu, ls, 8, 16);
            lrow[r] = lrow[r] * alpha + ls;
            #pragma unroll
            for (int c = 0; c < 4; c++) acc[r][c] *= alpha;
            s[r][0] = p0; s[r][1] = p1; s[r][2] = p2; s[r][3] = p3;
        }

        __syncthreads();   // all Kt reads done before overwriting with Ps
        #pragma unroll
        for (int r = 0; r < 4; r++) {
            *(float4*)(&KtPs[((((ty << 2) + r)) << 6) + (tx << 2)]) =
                make_float4(s[r][0], s[r][1], s[r][2], s[r][3]);
        }
        __syncthreads();

        // O += P V
        #pragma unroll 8
        for (int kk = 0; kk < 64; kk++) {
            float4 v4 = *(const float4*)(&Vs[(kk << 6) + (tx << 2)]);
            float p0 = KtPs[(((ty << 2) + 0) << 6) + kk];
            float p1 = KtPs[(((ty << 2) + 1) << 6) + kk];
            float p2 = KtPs[(((ty << 2) + 2) << 6) + kk];
            float p3 = KtPs[(((ty << 2) + 3) << 6) + kk];
            acc[0][0] += p0 * v4.x; acc[0][1] += p0 * v4.y; acc[0][2] += p0 * v4.z; acc[0][3] += p0 * v4.w;
            acc[1][0] += p1 * v4.x; acc[1][1] += p1 * v4.y; acc[1][2] += p1 * v4.z; acc[1][3] += p1 * v4.w;
            acc[2][0] += p2 * v4.x; acc[2][1] += p2 * v4.y; acc[2][2] += p2 * v4.z; acc[2][3] += p2 * v4.w;
            acc[3][0] += p3 * v4.x; acc[3][1] += p3 * v4.y; acc[3][2] += p3 * v4.z; acc[3][3] += p3 * v4.w;
        }
    }

    // Normalize and store context in [B, S, D] (natural for output GEMM)
    const int b = bh / NH;
    const int h = bh % NH;
    #pragma unroll
    for (int r = 0; r < 4; r++) {
        float inv = 1.0f / lrow[r];
        int q = qt * 64 + (ty << 2) + r;
        float4 o = make_float4(acc[r][0] * inv, acc[r][1] * inv,
                               acc[r][2] * inv, acc[r][3] * inv);
        *(float4*)(g_ctx + (size_t)(b * S_LEN + q) * DMODEL + (h << 6) + (tx << 2)) = o;
    }
}

// ---------------------------------------------------------------------------

extern "C" void kernel_launch(void* const* d_in, const int* in_sizes, int n_in,
                              void* d_out, int out_size)
{
    const float* x  = (const float*)d_in[0];
    const float* Wq = (const float*)d_in[1];
    const float* Wk = (const float*)d_in[2];
    const float* Wv = (const float*)d_in[3];
    const float* Wo = (const float*)d_in[4];
    const float* bo = (const float*)d_in[5];
    float* out = (float*)d_out;

    qkv_gemm<<<dim3(DMODEL / 64, MROWS / 64, 3), 256>>>(x, Wq, Wk, Wv);
    flash_attn<<<dim3(S_LEN / 64, BATCH * NH), 256>>>();
    out_gemm<<<dim3(DMODEL / 64, MROWS / 64), 256>>>(Wo, bo, out);
}

// round 2
// speedup vs baseline: 1.2307x; 1.2307x over previous
#include <cuda_runtime.h>

#define S_LEN  4096
#define BATCH  2
#define NH     12
#define DH     64
#define DMODEL 768
#define MROWS  (BATCH * S_LEN)   // 8192

// Scratch (static device globals; allocation-free rule)
__device__ __align__(128) float g_q[BATCH * NH * S_LEN * DH];
__device__ __align__(128) float g_k[BATCH * NH * S_LEN * DH];
__device__ __align__(128) float g_v[BATCH * NH * S_LEN * DH];
__device__ __align__(128) float g_ctx[MROWS * DMODEL];

// ---------------------------------------------------------------------------
// GEMM core: 128x128 tile, BK=8, 256 threads, 8x8 microtile, double-buffered.
// B fragment split (cols tx*4 and 64+tx*4) keeps LDS.128 phases conflict-free.
// ---------------------------------------------------------------------------

__device__ __forceinline__ void mm_step(const float (*As)[128], const float (*Bs)[128],
                                        float acc[8][8], int ty, int tx)
{
    #pragma unroll
    for (int kk = 0; kk < 8; kk++) {
        float4 a0 = *(const float4*)&As[kk][ty * 8];
        float4 a1 = *(const float4*)&As[kk][ty * 8 + 4];
        float4 b0 = *(const float4*)&Bs[kk][tx * 4];
        float4 b1 = *(const float4*)&Bs[kk][64 + tx * 4];
        float ar[8] = {a0.x, a0.y, a0.z, a0.w, a1.x, a1.y, a1.z, a1.w};
        float br[8] = {b0.x, b0.y, b0.z, b0.w, b1.x, b1.y, b1.z, b1.w};
        #pragma unroll
        for (int r = 0; r < 8; r++)
            #pragma unroll
            for (int c = 0; c < 8; c++)
                acc[r][c] += ar[r] * br[c];
    }
}

__global__ __launch_bounds__(256) void qkv_gemm(
    const float* __restrict__ x, const float* __restrict__ Wq,
    const float* __restrict__ Wk, const float* __restrict__ Wv)
{
    const float* W;
    float* out;
    float scale;
    if (blockIdx.z == 0)      { W = Wq; out = g_q; scale = 0.125f; }  // 1/sqrt(64) into Q
    else if (blockIdx.z == 1) { W = Wk; out = g_k; scale = 1.0f; }
    else                      { W = Wv; out = g_v; scale = 1.0f; }

    __shared__ __align__(16) float As[2][8][128];
    __shared__ __align__(16) float Bs[2][8][128];

    const int tid = threadIdx.x;
    const int tx = tid & 15, ty = tid >> 4;
    const int row0 = blockIdx.y * 128, col0 = blockIdx.x * 128;

    const int am = tid >> 1, ak = (tid & 1) << 2;
    const float* aPtr = x + (size_t)(row0 + am) * DMODEL + ak;
    const float* bPtr = W + (size_t)(tid >> 5) * DMODEL + col0 + ((tid & 31) << 2);

    // tile 0
    {
        float4 av = *(const float4*)aPtr;
        float4 bv = *(const float4*)bPtr;
        As[0][ak + 0][am] = av.x;
        As[0][ak + 1][am] = av.y;
        As[0][ak + 2][am] = av.z;
        As[0][ak + 3][am] = av.w;
        *(float4*)&Bs[0][tid >> 5][(tid & 31) << 2] = bv;
    }
    __syncthreads();

    float acc[8][8];
    #pragma unroll
    for (int r = 0; r < 8; r++)
        #pragma unroll
        for (int c = 0; c < 8; c++) acc[r][c] = 0.0f;

    int buf = 0;
    for (int k0 = 8; k0 < DMODEL; k0 += 8) {
        float4 av = *(const float4*)(aPtr + k0);
        float4 bv = *(const float4*)(bPtr + (size_t)k0 * DMODEL);
        mm_step(As[buf], Bs[buf], acc, ty, tx);
        As[buf ^ 1][ak + 0][am] = av.x;
        As[buf ^ 1][ak + 1][am] = av.y;
        As[buf ^ 1][ak + 2][am] = av.z;
        As[buf ^ 1][ak + 3][am] = av.w;
        *(float4*)&Bs[buf ^ 1][tid >> 5][(tid & 31) << 2] = bv;
        __syncthreads();
        buf ^= 1;
    }
    mm_step(As[buf], Bs[buf], acc, ty, tx);

    // Store to [B, H, S, DH]; col0 multiple of 128 -> two heads per tile.
    const int h0 = col0 >> 6;
    #pragma unroll
    for (int cg = 0; cg < 2; cg++) {
        int h = h0 + cg;
        #pragma unroll
        for (int r = 0; r < 8; r++) {
            int m = row0 + ty * 8 + r;
            int b = m >> 12;
            int s = m & 4095;
            float4 o = make_float4(acc[r][cg * 4 + 0] * scale, acc[r][cg * 4 + 1] * scale,
                                   acc[r][cg * 4 + 2] * scale, acc[r][cg * 4 + 3] * scale);
            *(float4*)(out + (((size_t)(b * NH + h) * S_LEN + s) << 6) + tx * 4) = o;
        }
    }
}

__global__ __launch_bounds__(256) void out_gemm(
    const float* __restrict__ Wo, const float* __restrict__ bo,
    float* __restrict__ out)
{
    __shared__ __align__(16) float As[2][8][128];
    __shared__ __align__(16) float Bs[2][8][128];

    const int tid = threadIdx.x;
    const int tx = tid & 15, ty = tid >> 4;
    const int row0 = blockIdx.y * 128, col0 = blockIdx.x * 128;

    const int am = tid >> 1, ak = (tid & 1) << 2;
    const float* aPtr = g_ctx + (size_t)(row0 + am) * DMODEL + ak;
    const float* bPtr = Wo + (size_t)(tid >> 5) * DMODEL + col0 + ((tid & 31) << 2);

    {
        float4 av = *(const float4*)aPtr;
        float4 bv = *(const float4*)bPtr;
        As[0][ak + 0][am] = av.x;
        As[0][ak + 1][am] = av.y;
        As[0][ak + 2][am] = av.z;
        As[0][ak + 3][am] = av.w;
        *(float4*)&Bs[0][tid >> 5][(tid & 31) << 2] = bv;
    }
    __syncthreads();

    float acc[8][8];
    #pragma unroll
    for (int r = 0; r < 8; r++)
        #pragma unroll
        for (int c = 0; c < 8; c++) acc[r][c] = 0.0f;

    int buf = 0;
    for (int k0 = 8; k0 < DMODEL; k0 += 8) {
        float4 av = *(const float4*)(aPtr + k0);
        float4 bv = *(const float4*)(bPtr + (size_t)k0 * DMODEL);
        mm_step(As[buf], Bs[buf], acc, ty, tx);
        As[buf ^ 1][ak + 0][am] = av.x;
        As[buf ^ 1][ak + 1][am] = av.y;
        As[buf ^ 1][ak + 2][am] = av.z;
        As[buf ^ 1][ak + 3][am] = av.w;
        *(float4*)&Bs[buf ^ 1][tid >> 5][(tid & 31) << 2] = bv;
        __syncthreads();
        buf ^= 1;
    }
    mm_step(As[buf], Bs[buf], acc, ty, tx);

    #pragma unroll
    for (int cg = 0; cg < 2; cg++) {
        float4 bias = *(const float4*)(bo + col0 + cg * 64 + tx * 4);
        #pragma unroll
        for (int r = 0; r < 8; r++) {
            int m = row0 + ty * 8 + r;
            float4 o = make_float4(acc[r][cg * 4 + 0] + bias.x, acc[r][cg * 4 + 1] + bias.y,
                                   acc[r][cg * 4 + 2] + bias.z, acc[r][cg * 4 + 3] + bias.w);
            *(float4*)(out + (size_t)m * DMODEL + col0 + cg * 64 + tx * 4) = o;
        }
    }
}

// ---------------------------------------------------------------------------
// Flash attention, causal. 64 q-rows per block, 64 keys per tile, 128 threads,
// 8x4 microtile. Q/K transposed+swizzled in smem; P read back as float4.
// ---------------------------------------------------------------------------

__global__ __launch_bounds__(128) void flash_attn()
{
    __shared__ __align__(16) float Qt[64 * 64];     // [d][m], swizzled
    __shared__ __align__(16) float KtPs[64 * 64];   // Kt [d][n] swizzled / Ps [m][n]
    __shared__ __align__(16) float Vs[64 * 64];     // [n][d]

    const int tid = threadIdx.x;
    const int tx = tid & 15, ty = tid >> 4;         // ty 0..7
    const int qt = blockIdx.x;
    const int bh = blockIdx.y;

    const float* qp = g_q + (size_t)bh * S_LEN * DH;
    const float* kp = g_k + (size_t)bh * S_LEN * DH;
    const float* vp = g_v + (size_t)bh * S_LEN * DH;

    // Load Q transposed + swizzled: (d, r) -> Qt[d*64 + ((r/4 ^ (d&15))<<2) + (r&3)]
    #pragma unroll
    for (int i = tid; i < 1024; i += 128) {
        int r = i >> 4;
        int d4 = (i & 15) << 2;
        float4 v = *(const float4*)(qp + (((size_t)qt * 64 + r) << 6) + d4);
        int j = r >> 2, sub = r & 3;
        Qt[(d4 + 0) * 64 + ((j ^ ((d4 + 0) & 15)) << 2) + sub] = v.x;
        Qt[(d4 + 1) * 64 + ((j ^ ((d4 + 1) & 15)) << 2) + sub] = v.y;
        Qt[(d4 + 2) * 64 + ((j ^ ((d4 + 2) & 15)) << 2) + sub] = v.z;
        Qt[(d4 + 3) * 64 + ((j ^ ((d4 + 3) & 15)) << 2) + sub] = v.w;
    }

    float mrow[8], lrow[8], acc[8][4];
    #pragma unroll
    for (int r = 0; r < 8; r++) {
        mrow[r] = -1e30f;
        lrow[r] = 0.0f;
        #pragma unroll
        for (int c = 0; c < 4; c++) acc[r][c] = 0.0f;
    }

    for (int kt = 0; kt <= qt; kt++) {
        __syncthreads();

        #pragma unroll
        for (int i = tid; i < 1024; i += 128) {
            int r = i >> 4;
            int d4 = (i & 15) << 2;
            float4 kv = *(const float4*)(kp + (((size_t)kt * 64 + r) << 6) + d4);
            int j = r >> 2, sub = r & 3;
            KtPs[(d4 + 0) * 64 + ((j ^ ((d4 + 0) & 15)) << 2) + sub] = kv.x;
            KtPs[(d4 + 1) * 64 + ((j ^ ((d4 + 1) & 15)) << 2) + sub] = kv.y;
            KtPs[(d4 + 2) * 64 + ((j ^ ((d4 + 2) & 15)) << 2) + sub] = kv.z;
            KtPs[(d4 + 3) * 64 + ((j ^ ((d4 + 3) & 15)) << 2) + sub] = kv.w;
            *(float4*)(&Vs[(r << 6) + d4]) =
                *(const float4*)(vp + (((size_t)kt * 64 + r) << 6) + d4);
        }
        __syncthreads();

        // S = Q K^T   (Q pre-scaled)
        float s[8][4];
        #pragma unroll
        for (int r = 0; r < 8; r++)
            #pragma unroll
            for (int c = 0; c < 4; c++) s[r][c] = 0.0f;

        #pragma unroll 4
        for (int kk = 0; kk < 64; kk++) {
            int sw = kk & 15;
            float4 q0 = *(const float4*)(&Qt[(kk << 6) + (((ty * 2) ^ sw) << 2)]);
            float4 q1 = *(const float4*)(&Qt[(kk << 6) + (((ty * 2 + 1) ^ sw) << 2)]);
            float4 k4 = *(const float4*)(&KtPs[(kk << 6) + ((tx ^ sw) << 2)]);
            float qv[8] = {q0.x, q0.y, q0.z, q0.w, q1.x, q1.y, q1.z, q1.w};
            float kv[4] = {k4.x, k4.y, k4.z, k4.w};
            #pragma unroll
            for (int r = 0; r < 8; r++)
                #pragma unroll
                for (int c = 0; c < 4; c++)
                    s[r][c] += qv[r] * kv[c];
        }

        if (kt == qt) {
            #pragma unroll
            for (int r = 0; r < 8; r++)
                #pragma unroll
                for (int c = 0; c < 4; c++)
                    if (tx * 4 + c > ty * 8 + r) s[r][c] = -1e30f;
        }

        // Online softmax; row = 16 tx lanes (width-16 shfl stays in half-warp)
        #pragma unroll
        for (int r = 0; r < 8; r++) {
            float mx = fmaxf(fmaxf(s[r][0], s[r][1]), fmaxf(s[r][2], s[r][3]));
            mx = fmaxf(mx, __shfl_xor_sync(0xffffffffu, mx, 1, 16));
            mx = fmaxf(mx, __shfl_xor_sync(0xffffffffu, mx, 2, 16));
            mx = fmaxf(mx, __shfl_xor_sync(0xffffffffu, mx, 4, 16));
            mx = fmaxf(mx, __shfl_xor_sync(0xffffffffu, mx, 8, 16));
            float mn = fmaxf(mrow[r], mx);
            float alpha = __expf(mrow[r] - mn);
            mrow[r] = mn;
            float p0 = __expf(s[r][0] - mn);
            float p1 = __expf(s[r][1] - mn);
            float p2 = __expf(s[r][2] - mn);
            float p3 = __expf(s[r][3] - mn);
            float ls = p0 + p1 + p2 + p3;
            ls += __shfl_xor_sync(0xffffffffu, ls, 1, 16);
            ls += __shfl_xor_sync(0xffffffffu, ls, 2, 16);
            ls += __shfl_xor_sync(0xffffffffu, ls, 4, 16);
            ls += __shfl_xor_sync(0xffffffffu, ls, 8, 16);
            lrow[r] = lrow[r] * alpha + ls;
            #pragma unroll
            for (int c = 0; c < 4; c++) acc[r][c] *= alpha;
            s[r][0] = p0; s[r][1] = p1; s[r][2] = p2; s[r][3] = p3;
        }

        __syncthreads();   // Kt reads done before P overwrite
        #pragma unroll
        for (int r = 0; r < 8; r++) {
            *(float4*)(&KtPs[((ty * 8 + r) << 6) + tx * 4]) =
                make_float4(s[r][0], s[r][1], s[r][2], s[r][3]);
        }
        __syncthreads();

        // O += P V  (P read as float4 over kk blocks of 4)
        #pragma unroll 4
        for (int kk4 = 0; kk4 < 16; kk4++) {
            float4 v0 = *(const float4*)(&Vs[((kk4 * 4 + 0) << 6) + tx * 4]);
            float4 v1 = *(const float4*)(&Vs[((kk4 * 4 + 1) << 6) + tx * 4]);
            float4 v2 = *(const float4*)(&Vs[((kk4 * 4 + 2) << 6) + tx * 4]);
            float4 v3 = *(const float4*)(&Vs[((kk4 * 4 + 3) << 6) + tx * 4]);
            #pragma unroll
            for (int r = 0; r < 8; r++) {
                float4 p4 = *(const float4*)(&KtPs[((ty * 8 + r) << 6) + kk4 * 4]);
                acc[r][0] += p4.x * v0.x + p4.y * v1.x + p4.z * v2.x + p4.w * v3.x;
                acc[r][1] += p4.x * v0.y + p4.y * v1.y + p4.z * v2.y + p4.w * v3.y;
                acc[r][2] += p4.x * v0.z + p4.y * v1.z + p4.z * v2.z + p4.w * v3.z;
                acc[r][3] += p4.x * v0.w + p4.y * v1.w + p4.z * v2.w + p4.w * v3.w;
            }
        }
    }

    // Normalize and store context in [B, S, D]
    const int b = bh / NH;
    const int h = bh % NH;
    #pragma unroll
    for (int r = 0; r < 8; r++) {
        float inv = 1.0f / lrow[r];
        int q = qt * 64 + ty * 8 + r;
        float4 o = make_float4(acc[r][0] * inv, acc[r][1] * inv,
                               acc[r][2] * inv, acc[r][3] * inv);
        *(float4*)(g_ctx + (size_t)(b * S_LEN + q) * DMODEL + (h << 6) + tx * 4) = o;
    }
}

// ---------------------------------------------------------------------------

extern "C" void kernel_launch(void* const* d_in, const int* in_sizes, int n_in,
                              void* d_out, int out_size)
{
    const float* x  = (const float*)d_in[0];
    const float* Wq = (const float*)d_in[1];
    const float* Wk = (const float*)d_in[2];
    const float* Wv = (const float*)d_in[3];
    const float* Wo = (const float*)d_in[4];
    const float* bo = (const float*)d_in[5];
    float* out = (float*)d_out;

    qkv_gemm<<<dim3(DMODEL / 128, MROWS / 128, 3), 256>>>(x, Wq, Wk, Wv);
    flash_attn<<<dim3(S_LEN / 64, BATCH * NH), 128>>>();
    out_gemm<<<dim3(DMODEL / 128, MROWS / 128), 256>>>(Wo, bo, out);
}